// round 15
// baseline (speedup 1.0000x reference)
#include <cuda_runtime.h>
#include <math.h>

#define B_ 2
#define C_ 10
#define N_ 100
#define M_ 50
#define HW 9216      // 96*96
#define HPWP 576     // 24*24
#define KSPLIT 72
#define KCHUNK 128   // 9216/72
#define KK 32
#define STR 34
#define T_FLOATS (M_ * STR)
#define PG_FLOATS (N_ * STR)
#define BUF_FLOATS (T_FLOATS + 2 * PG_FLOATS)  // 8500
#define DSMEM_BYTES (2 * BUF_FLOATS * 4)       // 68000
#define NQ 8
#define TWO_PI_F 6.2831854820251465f
#define PI_F 3.1415927410125732f

typedef unsigned long long ull;

// ---------------- scratch ----------------
__device__ __align__(16) float g_P[B_ * N_ * HW];
__device__ __align__(16) float g_G[B_ * N_ * HW];
__device__ __align__(16) float g_Sp[B_ * N_];
__device__ __align__(16) float g_F0c[B_ * N_ * NQ];
__device__ __align__(16) float g_St[B_ * M_];
// layout: [b][n][m][ks]
__device__ __align__(16) float g_part1[B_ * N_ * M_ * KSPLIT];
__device__ __align__(16) float g_part2[B_ * N_ * M_ * KSPLIT];

__constant__ float c_w[4] = {0.625f, 0.875f, 0.125f, 0.375f};

#define FMA2(d, a, b, c) \
    asm("fma.rn.f32x2 %0, %1, %2, %3;" : "=l"(d) : "l"(a), "l"(b), "l"(c))

// paired reduce over 288 threads (9 warps); valid in thread 0
__device__ __forceinline__ float2 blockReduceSum2_288(float a, float b, float2* sh) {
    int lane = threadIdx.x & 31;
    int wid = threadIdx.x >> 5;
    #pragma unroll
    for (int o = 16; o > 0; o >>= 1) {
        a += __shfl_down_sync(0xffffffffu, a, o);
        b += __shfl_down_sync(0xffffffffu, b, o);
    }
    if (lane == 0) sh[wid] = make_float2(a, b);
    __syncthreads();
    float2 v = (threadIdx.x < 9) ? sh[threadIdx.x] : make_float2(0.f, 0.f);
    if (wid == 0) {
        #pragma unroll
        for (int o = 8; o > 0; o >>= 1) {
            v.x += __shfl_down_sync(0xffffffffu, v.x, o);
            v.y += __shfl_down_sync(0xffffffffu, v.y, o);
        }
    }
    return v;
}

// ------ kernel 1: St blocks 0..99 FIRST (long, overlap), conv 100..1699 ---
__global__ void __launch_bounds__(288) k_pre(const float* __restrict__ pred_mask,
                                             const float* __restrict__ tmask) {
    __shared__ float sm[HPWP];
    __shared__ float2 red2[9];
    int tid = threadIdx.x;
    int bc = blockIdx.x;

    if (bc < 100) {
        int bm = bc;
        const float4* src = (const float4*)(tmask + (size_t)bm * HW);
        float s = 0.0f;
        #pragma unroll
        for (int i = 0; i < 8; i++) {
            int idx = tid + i * 288;
            if (idx < HW / 4) {
                float4 v = src[idx];
                s += (fabsf(v.x) + fabsf(v.y)) + (fabsf(v.z) + fabsf(v.w));
            }
        }
        float2 ts = blockReduceSum2_288(s, 0.0f, red2);
        if (tid == 0) g_St[bm] = ts.x;
    } else {
        int cc = bc - 100;
        int bn = cc >> 3;
        int q  = cc & 7;

        float2 v2 = ((const float2*)(pred_mask + (size_t)bn * HPWP))[tid];
        *(float2*)(sm + (tid << 1)) = v2;
        float ssum = (q == 0) ? (v2.x + v2.y) : 0.0f;
        __syncthreads();

        float* Pout = g_P + (size_t)bn * HW + q * (12 * 96);
        float* Gout = g_G + (size_t)bn * HW + q * (12 * 96);

        int r = tid / 24;
        int j = tid - r * 24;
        int yg = q * 12 + r;
        int iy = (yg - 2) >> 2;
        float wy = c_w[yg & 3];
        int iy0 = max(iy, 0) * 24, iy1 = min(iy + 1, 23) * 24;
        int cm = max(j - 1, 0), cp = min(j + 1, 23);

        float a0 = sm[iy0 + cm], a1 = sm[iy0 + j], a2 = sm[iy0 + cp];
        float b0 = sm[iy1 + cm], b1 = sm[iy1 + j], b2 = sm[iy1 + cp];

        float t0 = a0 + 0.625f * (a1 - a0);
        float t1 = a0 + 0.875f * (a1 - a0);
        float t2 = a1 + 0.125f * (a2 - a1);
        float t3 = a1 + 0.375f * (a2 - a1);
        float u0 = b0 + 0.625f * (b1 - b0);
        float u1 = b0 + 0.875f * (b1 - b0);
        float u2 = b1 + 0.125f * (b2 - b1);
        float u3 = b1 + 0.375f * (b2 - b1);

        float pv[4];
        pv[0] = t0 + wy * (u0 - t0);
        pv[1] = t1 + wy * (u1 - t1);
        pv[2] = t2 + wy * (u2 - t2);
        pv[3] = t3 + wy * (u3 - t3);

        float gv[4];
        float sf0 = 0.0f;
        #pragma unroll
        for (int k = 0; k < 4; k++) {
            float pc = fminf(fmaxf(pv[k], 0.001f), 0.999f);
            float omc = 1.0f - pc;
            float f1 = 0.25f * (-__logf(pc)) * omc * omc;
            float f0 = 0.75f * (-__logf(omc)) * pc * pc;
            gv[k] = f1 - f0;
            sf0 += f0;
        }
        int o = r * 96 + j * 4;
        *(float4*)(Pout + o) = make_float4(pv[0], pv[1], pv[2], pv[3]);
        *(float4*)(Gout + o) = make_float4(gv[0], gv[1], gv[2], gv[3]);

        float2 ts = blockReduceSum2_288(sf0, ssum, red2);
        if (tid == 0) {
            g_F0c[bn * NQ + q] = ts.x;
            if (q == 0) g_Sp[bn] = 16.0f * ts.y;
        }
    }
}

// ------ kernel 2: dots, 1024 threads, tile 5m x 1n x 2 dots ------
__global__ void __launch_bounds__(1024) k_dots(const float* __restrict__ tmask) {
    extern __shared__ __align__(16) float dsm[];
    int ks = blockIdx.x;
    int b  = blockIdx.y;
    int tid = threadIdx.x;

    int mg = tid % 10;
    int n  = tid / 10;          // 0..99 active (tid < 1000)
    bool active = tid < 1000;
    int m0 = mg * 5;

    const float* Tbase = tmask + (size_t)b * M_ * HW;
    const float* Pbase = g_P + (size_t)b * N_ * HW;
    const float* Gbase = g_G + (size_t)b * N_ * HW;

    ull a1[5], a2[5];
    #pragma unroll
    for (int i = 0; i < 5; i++) { a1[i] = 0ULL; a2[i] = 0ULL; }

    // loaders: T 400 f4 (tid<400), P/G 800 f4 each (tid<800)
    int rowT = tid >> 3, cT = (tid & 7) << 2;   // row 0..49 for tid<400
    int rowP = tid >> 3, cP = (tid & 7) << 2;   // row 0..99 for tid<800
    bool hasT = tid < 400;
    bool hasPG = tid < 800;

    float4 ft, fp, fg;
    int kbeg = ks * KCHUNK;

    // prefetch stage 0
    {
        int k0 = kbeg;
        if (hasT) ft = *(const float4*)(Tbase + (size_t)rowT * HW + k0 + cT);
        if (hasPG) {
            fp = *(const float4*)(Pbase + (size_t)rowP * HW + k0 + cP);
            fg = *(const float4*)(Gbase + (size_t)rowP * HW + k0 + cP);
        }
        float* bt = dsm;
        float* bp = bt + T_FLOATS;
        float* bg = bp + PG_FLOATS;
        if (hasT) {
            float* d = bt + rowT * STR + cT;
            *(float2*)(d) = make_float2(ft.x, ft.y);
            *(float2*)(d + 2) = make_float2(ft.z, ft.w);
        }
        if (hasPG) {
            float* d = bp + rowP * STR + cP;
            *(float2*)(d) = make_float2(fp.x, fp.y);
            *(float2*)(d + 2) = make_float2(fp.z, fp.w);
            float* d2 = bg + rowP * STR + cP;
            *(float2*)(d2) = make_float2(fg.x, fg.y);
            *(float2*)(d2 + 2) = make_float2(fg.z, fg.w);
        }
    }
    __syncthreads();

    #pragma unroll
    for (int s = 0; s < KCHUNK / KK; s++) {
        int cur = s & 1;
        if (s < KCHUNK / KK - 1) {
            int k0 = kbeg + (s + 1) * KK;
            if (hasT) ft = *(const float4*)(Tbase + (size_t)rowT * HW + k0 + cT);
            if (hasPG) {
                fp = *(const float4*)(Pbase + (size_t)rowP * HW + k0 + cP);
                fg = *(const float4*)(Gbase + (size_t)rowP * HW + k0 + cP);
            }
        }

        {
            const float* bt = dsm + cur * BUF_FLOATS;
            const ull* sh_t2 = (const ull*)bt;
            const ull* sh_p2 = (const ull*)(bt + T_FLOATS);
            const ull* sh_g2 = (const ull*)(bt + T_FLOATS + PG_FLOATS);
            if (active) {
                #pragma unroll
                for (int kp = 0; kp < KK / 2; kp++) {
                    ull tv[5];
                    #pragma unroll
                    for (int i = 0; i < 5; i++) tv[i] = sh_t2[(m0 + i) * (STR / 2) + kp];
                    ull pvv = sh_p2[n * (STR / 2) + kp];
                    ull gvv = sh_g2[n * (STR / 2) + kp];
                    #pragma unroll
                    for (int i = 0; i < 5; i++) {
                        FMA2(a1[i], tv[i], pvv, a1[i]);
                        FMA2(a2[i], tv[i], gvv, a2[i]);
                    }
                }
            }
        }

        if (s < KCHUNK / KK - 1) {
            float* bt = dsm + (cur ^ 1) * BUF_FLOATS;
            float* bp = bt + T_FLOATS;
            float* bg = bp + PG_FLOATS;
            if (hasT) {
                float* d = bt + rowT * STR + cT;
                *(float2*)(d) = make_float2(ft.x, ft.y);
                *(float2*)(d + 2) = make_float2(ft.z, ft.w);
            }
            if (hasPG) {
                float* d = bp + rowP * STR + cP;
                *(float2*)(d) = make_float2(fp.x, fp.y);
                *(float2*)(d + 2) = make_float2(fp.z, fp.w);
                float* d2 = bg + rowP * STR + cP;
                *(float2*)(d2) = make_float2(fg.x, fg.y);
                *(float2*)(d2 + 2) = make_float2(fg.z, fg.w);
            }
        }
        __syncthreads();
    }

    if (active) {
        #pragma unroll
        for (int i = 0; i < 5; i++) {
            int m = m0 + i;
            size_t idx = ((size_t)(b * N_ + n) * M_ + m) * KSPLIT + ks;
            float2 v1 = *(float2*)&a1[i];
            float2 v2 = *(float2*)&a2[i];
            g_part1[idx] = v1.x + v1.y;
            g_part2[idx] = v2.x + v2.y;
        }
    }
}

// ------ kernel 3: assemble (2 threads per output) ------
__global__ void k_assemble(const float* __restrict__ pred_prob,
                           const float* __restrict__ pred_mom,
                           const int*   __restrict__ tcls,
                           const float* __restrict__ tmom,
                           float* __restrict__ out) {
    int gid = blockIdx.x * blockDim.x + threadIdx.x;
    int oid = gid >> 1;
    int part = gid & 1;
    bool valid = oid < B_ * N_ * M_;
    int o = valid ? oid : 0;
    int m = o % M_;
    int n = (o / M_) % N_;
    int b = o / (N_ * M_);

    size_t base = (size_t)o * KSPLIT + part * (KSPLIT / 2);
    const float4* p1 = (const float4*)(g_part1 + base);
    const float4* p2 = (const float4*)(g_part2 + base);
    float dot1 = 0.f, dot2 = 0.f;
    #pragma unroll
    for (int i = 0; i < KSPLIT / 8; i++) {
        float4 v = p1[i];
        float4 w = p2[i];
        dot1 += (v.x + v.y) + (v.z + v.w);
        dot2 += (w.x + w.y) + (w.z + w.w);
    }
    float f0s = 0.f;
    {
        const float4* pf = (const float4*)(g_F0c + (size_t)(b * N_ + n) * NQ + part * 4);
        float4 x = pf[0];
        f0s = (x.x + x.y) + (x.z + x.w);
    }
    dot1 += __shfl_down_sync(0xffffffffu, dot1, 1);
    dot2 += __shfl_down_sync(0xffffffffu, dot2, 1);
    f0s  += __shfl_down_sync(0xffffffffu, f0s, 1);

    if (!valid || part) return;

    int cls = tcls[b * M_ + m];
    if (cls <= 0) { out[oid] = 100000.0f; return; }

    float Sp = g_Sp[b * N_ + n];
    float St = g_St[b * M_ + m];
    float pos = Sp + St;
    float cost_dice = 1.0f - 2.0f * dot1 / (pos + 0.001f);
    float cost_focal = (f0s + dot2) * (1.0f / (float)HW);
    float cost_class = -pred_prob[((size_t)b * C_ + cls) * N_ + n];

    const float* pmv = pred_mom + (size_t)(b * N_ + n) * 4;
    float p0 = __expf(fminf(pmv[0], 10.0f));
    float p1f = TWO_PI_F / (1.0f + __expf(-pmv[1]));
    float p2f = TWO_PI_F / (1.0f + __expf(-pmv[2]));
    float p3 = __expf(fminf(pmv[3], 10.0f));
    const float* tmv = tmom + (size_t)(b * M_ + m) * 4;
    float t0 = tmv[0], t1 = tmv[1], t2 = tmv[2], t3 = tmv[3];

    float pe = (t2 - p2f > PI_F) ? TWO_PI_F : 0.0f;
    float te = (p2f - t2 > PI_F) ? TWO_PI_F : 0.0f;
    float l1 = (fabsf(p0 / (t0 + 0.001f) - 1.0f)
              + fabsf(p1f / (t1 + 0.001f) - 1.0f)
              + fabsf((p2f + pe) / (t2 + te + 0.001f) - 1.0f)
              + fabsf(p3 / (t3 + 0.001f) - 1.0f)) * 0.25f;

    float w1 = p0, x1 = p1f, y1 = p2f, h1 = p3;
    float w2 = t0, x2 = t1, y2 = t2, h2 = t3;
    float y1e = (y2 - y1 > PI_F) ? TWO_PI_F : 0.0f;
    float y2e = (y1 - y2 > PI_F) ? TWO_PI_F : 0.0f;
    y1 += y1e;
    y2 += y2e;
    float r1 = x1 + w1 * 0.5f, l1b = x1 - w1 * 0.5f;
    float r2 = x2 + w2 * 0.5f, l2b = x2 - w2 * 0.5f;
    float u1 = y1 + h1 * 0.5f, d1 = y1 - h1 * 0.5f;
    float u2 = y2 + h2 * 0.5f, d2 = y2 - h2 * 0.5f;
    float w = fminf(r1, r2) - fmaxf(l1b, l2b);
    float h = fminf(u1, u2) - fmaxf(d1, d2);
    float iou = (w > 0.0f && h > 0.0f)
                ? (w * h) / (w1 * h1 + w2 * h2 - w * h + 0.001f) : 0.0f;
    float cw = fmaxf(r1, r2) - fminf(l1b, l2b);
    float ch = fmaxf(u1, u2) - fminf(d1, d2);
    float cw2 = cw * cw, ch2 = ch * ch;
    float dw = w1 - w2, dh = h1 - h2;
    float rho_w = dw * dw / (cw2 + 0.001f);
    float rho_h = dh * dh / (ch2 + 0.001f);
    float dx = x1 - x2, dy = y1 - y2;
    float rho_d = (dx * dx + dy * dy) / (cw2 + ch2 + 0.001f);
    float ce = 1.0f - iou + rho_d + rho_w + rho_h;

    out[oid] = 0.25f * cost_focal + 0.75f * cost_dice + cost_class
             + 0.8f * l1 + 0.2f * ce;
}

extern "C" void kernel_launch(void* const* d_in, const int* in_sizes, int n_in,
                              void* d_out, int out_size) {
    const float* pred_prob = (const float*)d_in[0];
    const float* pred_mask = (const float*)d_in[1];
    const float* pred_mom  = (const float*)d_in[2];
    const int*   tcls      = (const int*)d_in[3];
    const float* tmask     = (const float*)d_in[4];
    const float* tmom      = (const float*)d_in[5];
    float* out = (float*)d_out;

    static int configured = 0;
    if (!configured) {
        cudaFuncSetAttribute(k_dots, cudaFuncAttributeMaxDynamicSharedMemorySize,
                             DSMEM_BYTES);
        configured = 1;
    }

    k_pre<<<1700, 288>>>(pred_mask, tmask);
    dim3 grid(KSPLIT, B_);
    k_dots<<<grid, 1024, DSMEM_BYTES>>>(tmask);
    int total_threads = 2 * B_ * N_ * M_;
    k_assemble<<<(total_threads + 255) / 256, 256>>>(pred_prob, pred_mom, tcls, tmom, out);
}

// round 16
// speedup vs baseline: 1.0127x; 1.0127x over previous
#include <cuda_runtime.h>
#include <cuda_pipeline.h>
#include <math.h>

#define B_ 2
#define C_ 10
#define N_ 100
#define M_ 50
#define HW 9216      // 96*96
#define HPWP 576     // 24*24
#define KSPLIT 72
#define KCHUNK 128   // 9216/72
#define KK 32
#define STR 34
#define T_FLOATS (M_ * STR)
#define PG_FLOATS (N_ * STR)
#define BUF_FLOATS (T_FLOATS + 2 * PG_FLOATS)  // 8500
#define DSMEM_BYTES (2 * BUF_FLOATS * 4)       // 68000
#define NQ 8
#define NSTAGE (KCHUNK / KK)                   // 4
#define TWO_PI_F 6.2831854820251465f
#define PI_F 3.1415927410125732f

typedef unsigned long long ull;

// ---------------- scratch ----------------
__device__ __align__(16) float g_P[B_ * N_ * HW];
__device__ __align__(16) float g_G[B_ * N_ * HW];
__device__ __align__(16) float g_Sp[B_ * N_];
__device__ __align__(16) float g_F0c[B_ * N_ * NQ];
__device__ __align__(16) float g_St[B_ * M_];
// layout: [b][n][m][ks]
__device__ __align__(16) float g_part1[B_ * N_ * M_ * KSPLIT];
__device__ __align__(16) float g_part2[B_ * N_ * M_ * KSPLIT];

__constant__ float c_w[4] = {0.625f, 0.875f, 0.125f, 0.375f};

#define FMA2(d, a, b, c) \
    asm("fma.rn.f32x2 %0, %1, %2, %3;" : "=l"(d) : "l"(a), "l"(b), "l"(c))

// paired reduce over 288 threads (9 warps); valid in thread 0
__device__ __forceinline__ float2 blockReduceSum2_288(float a, float b, float2* sh) {
    int lane = threadIdx.x & 31;
    int wid = threadIdx.x >> 5;
    #pragma unroll
    for (int o = 16; o > 0; o >>= 1) {
        a += __shfl_down_sync(0xffffffffu, a, o);
        b += __shfl_down_sync(0xffffffffu, b, o);
    }
    if (lane == 0) sh[wid] = make_float2(a, b);
    __syncthreads();
    float2 v = (threadIdx.x < 9) ? sh[threadIdx.x] : make_float2(0.f, 0.f);
    if (wid == 0) {
        #pragma unroll
        for (int o = 8; o > 0; o >>= 1) {
            v.x += __shfl_down_sync(0xffffffffu, v.x, o);
            v.y += __shfl_down_sync(0xffffffffu, v.y, o);
        }
    }
    return v;
}

// ------ kernel 1: St blocks 0..99 FIRST (long, overlap), conv 100..1699 ---
__global__ void __launch_bounds__(288) k_pre(const float* __restrict__ pred_mask,
                                             const float* __restrict__ tmask) {
    __shared__ float sm[HPWP];
    __shared__ float2 red2[9];
    int tid = threadIdx.x;
    int bc = blockIdx.x;

    if (bc < 100) {
        int bm = bc;
        const float4* src = (const float4*)(tmask + (size_t)bm * HW);
        float s = 0.0f;
        #pragma unroll
        for (int i = 0; i < 8; i++) {
            int idx = tid + i * 288;
            if (idx < HW / 4) {
                float4 v = src[idx];
                s += (fabsf(v.x) + fabsf(v.y)) + (fabsf(v.z) + fabsf(v.w));
            }
        }
        float2 ts = blockReduceSum2_288(s, 0.0f, red2);
        if (tid == 0) g_St[bm] = ts.x;
    } else {
        int cc = bc - 100;
        int bn = cc >> 3;
        int q  = cc & 7;

        float2 v2 = ((const float2*)(pred_mask + (size_t)bn * HPWP))[tid];
        *(float2*)(sm + (tid << 1)) = v2;
        float ssum = (q == 0) ? (v2.x + v2.y) : 0.0f;
        __syncthreads();

        float* Pout = g_P + (size_t)bn * HW + q * (12 * 96);
        float* Gout = g_G + (size_t)bn * HW + q * (12 * 96);

        int r = tid / 24;
        int j = tid - r * 24;
        int yg = q * 12 + r;
        int iy = (yg - 2) >> 2;
        float wy = c_w[yg & 3];
        int iy0 = max(iy, 0) * 24, iy1 = min(iy + 1, 23) * 24;
        int cm = max(j - 1, 0), cp = min(j + 1, 23);

        float a0 = sm[iy0 + cm], a1 = sm[iy0 + j], a2 = sm[iy0 + cp];
        float b0 = sm[iy1 + cm], b1 = sm[iy1 + j], b2 = sm[iy1 + cp];

        float t0 = a0 + 0.625f * (a1 - a0);
        float t1 = a0 + 0.875f * (a1 - a0);
        float t2 = a1 + 0.125f * (a2 - a1);
        float t3 = a1 + 0.375f * (a2 - a1);
        float u0 = b0 + 0.625f * (b1 - b0);
        float u1 = b0 + 0.875f * (b1 - b0);
        float u2 = b1 + 0.125f * (b2 - b1);
        float u3 = b1 + 0.375f * (b2 - b1);

        float pv[4];
        pv[0] = t0 + wy * (u0 - t0);
        pv[1] = t1 + wy * (u1 - t1);
        pv[2] = t2 + wy * (u2 - t2);
        pv[3] = t3 + wy * (u3 - t3);

        float gv[4];
        float sf0 = 0.0f;
        #pragma unroll
        for (int k = 0; k < 4; k++) {
            float pc = fminf(fmaxf(pv[k], 0.001f), 0.999f);
            float omc = 1.0f - pc;
            float f1 = 0.25f * (-__logf(pc)) * omc * omc;
            float f0 = 0.75f * (-__logf(omc)) * pc * pc;
            gv[k] = f1 - f0;
            sf0 += f0;
        }
        int o = r * 96 + j * 4;
        *(float4*)(Pout + o) = make_float4(pv[0], pv[1], pv[2], pv[3]);
        *(float4*)(Gout + o) = make_float4(gv[0], gv[1], gv[2], gv[3]);

        float2 ts = blockReduceSum2_288(sf0, ssum, red2);
        if (tid == 0) {
            g_F0c[bn * NQ + q] = ts.x;
            if (q == 0) g_Sp[bn] = 16.0f * ts.y;
        }
    }
}

// issue all cp.async copies for one stage
__device__ __forceinline__ void issue_stage(float* buf,
                                            const float* __restrict__ Tbase,
                                            const float* __restrict__ Pbase,
                                            const float* __restrict__ Gbase,
                                            int k0, int tid) {
    float* bt = buf;
    float* bp = buf + T_FLOATS;
    float* bg = bp + PG_FLOATS;
    if (tid < 400) {
        int row = tid >> 3, c4 = (tid & 7) << 2;
        const float* src = Tbase + (size_t)row * HW + k0 + c4;
        float* d = bt + row * STR + c4;
        __pipeline_memcpy_async(d, src, 8);
        __pipeline_memcpy_async(d + 2, src + 2, 8);
    }
    {
        int row = tid >> 3, c4 = (tid & 7) << 2;   // rows 0..63
        const float* srcp = Pbase + (size_t)row * HW + k0 + c4;
        float* dp = bp + row * STR + c4;
        __pipeline_memcpy_async(dp, srcp, 8);
        __pipeline_memcpy_async(dp + 2, srcp + 2, 8);
        const float* srcg = Gbase + (size_t)row * HW + k0 + c4;
        float* dg = bg + row * STR + c4;
        __pipeline_memcpy_async(dg, srcg, 8);
        __pipeline_memcpy_async(dg + 2, srcg + 2, 8);
    }
    if (tid < 288) {
        int e = tid + 512;
        int row = e >> 3, c4 = (e & 7) << 2;       // rows 64..99
        const float* srcp = Pbase + (size_t)row * HW + k0 + c4;
        float* dp = bp + row * STR + c4;
        __pipeline_memcpy_async(dp, srcp, 8);
        __pipeline_memcpy_async(dp + 2, srcp + 2, 8);
        const float* srcg = Gbase + (size_t)row * HW + k0 + c4;
        float* dg = bg + row * STR + c4;
        __pipeline_memcpy_async(dg, srcg, 8);
        __pipeline_memcpy_async(dg + 2, srcg + 2, 8);
    }
}

// ------ kernel 2: dots, cp.async pipeline, 2 blocks/SM ------
__global__ void __launch_bounds__(512, 2) k_dots(const float* __restrict__ tmask) {
    extern __shared__ __align__(16) float dsm[];
    int ks = blockIdx.x;
    int b  = blockIdx.y;
    int tid = threadIdx.x;

    int mg = tid % 10;
    int ng = tid / 10;
    bool active = tid < 500;
    int m0 = mg * 5;
    int n0 = ng * 2;

    const float* Tbase = tmask + (size_t)b * M_ * HW;
    const float* Pbase = g_P + (size_t)b * N_ * HW;
    const float* Gbase = g_G + (size_t)b * N_ * HW;

    ull a1[5][2], a2[5][2];
    #pragma unroll
    for (int i = 0; i < 5; i++)
        #pragma unroll
        for (int j = 0; j < 2; j++) { a1[i][j] = 0ULL; a2[i][j] = 0ULL; }

    int kbeg = ks * KCHUNK;

    // prologue: issue stage 0
    issue_stage(dsm, Tbase, Pbase, Gbase, kbeg, tid);
    __pipeline_commit();

    #pragma unroll
    for (int s = 0; s < NSTAGE; s++) {
        int cur = s & 1;
        if (s + 1 < NSTAGE) {
            issue_stage(dsm + (cur ^ 1) * BUF_FLOATS, Tbase, Pbase, Gbase,
                        kbeg + (s + 1) * KK, tid);
            __pipeline_commit();
            __pipeline_wait_prior(1);
        } else {
            __pipeline_wait_prior(0);
        }
        __syncthreads();   // stage s data visible to all

        {
            const float* bt = dsm + cur * BUF_FLOATS;
            const ull* sh_t2 = (const ull*)bt;
            const ull* sh_p2 = (const ull*)(bt + T_FLOATS);
            const ull* sh_g2 = (const ull*)(bt + T_FLOATS + PG_FLOATS);
            if (active) {
                #pragma unroll
                for (int kp = 0; kp < KK / 2; kp++) {
                    ull tv[5], pv[2], gv[2];
                    #pragma unroll
                    for (int i = 0; i < 5; i++) tv[i] = sh_t2[(m0 + i) * (STR / 2) + kp];
                    #pragma unroll
                    for (int j = 0; j < 2; j++) {
                        pv[j] = sh_p2[(n0 + j) * (STR / 2) + kp];
                        gv[j] = sh_g2[(n0 + j) * (STR / 2) + kp];
                    }
                    #pragma unroll
                    for (int i = 0; i < 5; i++) {
                        #pragma unroll
                        for (int j = 0; j < 2; j++) {
                            FMA2(a1[i][j], tv[i], pv[j], a1[i][j]);
                            FMA2(a2[i][j], tv[i], gv[j], a2[i][j]);
                        }
                    }
                }
            }
        }
        __syncthreads();   // done reading buf cur before it's refilled at s+2
    }

    if (active) {
        #pragma unroll
        for (int i = 0; i < 5; i++) {
            #pragma unroll
            for (int j = 0; j < 2; j++) {
                int n = n0 + j;
                int m = m0 + i;
                size_t idx = ((size_t)(b * N_ + n) * M_ + m) * KSPLIT + ks;
                float2 v1 = *(float2*)&a1[i][j];
                float2 v2 = *(float2*)&a2[i][j];
                g_part1[idx] = v1.x + v1.y;
                g_part2[idx] = v2.x + v2.y;
            }
        }
    }
}

// ------ kernel 3: assemble (2 threads per output) ------
__global__ void k_assemble(const float* __restrict__ pred_prob,
                           const float* __restrict__ pred_mom,
                           const int*   __restrict__ tcls,
                           const float* __restrict__ tmom,
                           float* __restrict__ out) {
    int gid = blockIdx.x * blockDim.x + threadIdx.x;
    int oid = gid >> 1;
    int part = gid & 1;
    bool valid = oid < B_ * N_ * M_;
    int o = valid ? oid : 0;
    int m = o % M_;
    int n = (o / M_) % N_;
    int b = o / (N_ * M_);

    size_t base = (size_t)o * KSPLIT + part * (KSPLIT / 2);
    const float4* p1 = (const float4*)(g_part1 + base);
    const float4* p2 = (const float4*)(g_part2 + base);
    float dot1 = 0.f, dot2 = 0.f;
    #pragma unroll
    for (int i = 0; i < KSPLIT / 8; i++) {
        float4 v = p1[i];
        float4 w = p2[i];
        dot1 += (v.x + v.y) + (v.z + v.w);
        dot2 += (w.x + w.y) + (w.z + w.w);
    }
    float f0s = 0.f;
    {
        const float4* pf = (const float4*)(g_F0c + (size_t)(b * N_ + n) * NQ + part * 4);
        float4 x = pf[0];
        f0s = (x.x + x.y) + (x.z + x.w);
    }
    dot1 += __shfl_down_sync(0xffffffffu, dot1, 1);
    dot2 += __shfl_down_sync(0xffffffffu, dot2, 1);
    f0s  += __shfl_down_sync(0xffffffffu, f0s, 1);

    if (!valid || part) return;

    int cls = tcls[b * M_ + m];
    if (cls <= 0) { out[oid] = 100000.0f; return; }

    float Sp = g_Sp[b * N_ + n];
    float St = g_St[b * M_ + m];
    float pos = Sp + St;
    float cost_dice = 1.0f - 2.0f * dot1 / (pos + 0.001f);
    float cost_focal = (f0s + dot2) * (1.0f / (float)HW);
    float cost_class = -pred_prob[((size_t)b * C_ + cls) * N_ + n];

    const float* pmv = pred_mom + (size_t)(b * N_ + n) * 4;
    float p0 = __expf(fminf(pmv[0], 10.0f));
    float p1f = TWO_PI_F / (1.0f + __expf(-pmv[1]));
    float p2f = TWO_PI_F / (1.0f + __expf(-pmv[2]));
    float p3 = __expf(fminf(pmv[3], 10.0f));
    const float* tmv = tmom + (size_t)(b * M_ + m) * 4;
    float t0 = tmv[0], t1 = tmv[1], t2 = tmv[2], t3 = tmv[3];

    float pe = (t2 - p2f > PI_F) ? TWO_PI_F : 0.0f;
    float te = (p2f - t2 > PI_F) ? TWO_PI_F : 0.0f;
    float l1 = (fabsf(p0 / (t0 + 0.001f) - 1.0f)
              + fabsf(p1f / (t1 + 0.001f) - 1.0f)
              + fabsf((p2f + pe) / (t2 + te + 0.001f) - 1.0f)
              + fabsf(p3 / (t3 + 0.001f) - 1.0f)) * 0.25f;

    float w1 = p0, x1 = p1f, y1 = p2f, h1 = p3;
    float w2 = t0, x2 = t1, y2 = t2, h2 = t3;
    float y1e = (y2 - y1 > PI_F) ? TWO_PI_F : 0.0f;
    float y2e = (y1 - y2 > PI_F) ? TWO_PI_F : 0.0f;
    y1 += y1e;
    y2 += y2e;
    float r1 = x1 + w1 * 0.5f, l1b = x1 - w1 * 0.5f;
    float r2 = x2 + w2 * 0.5f, l2b = x2 - w2 * 0.5f;
    float u1 = y1 + h1 * 0.5f, d1 = y1 - h1 * 0.5f;
    float u2 = y2 + h2 * 0.5f, d2 = y2 - h2 * 0.5f;
    float w = fminf(r1, r2) - fmaxf(l1b, l2b);
    float h = fminf(u1, u2) - fmaxf(d1, d2);
    float iou = (w > 0.0f && h > 0.0f)
                ? (w * h) / (w1 * h1 + w2 * h2 - w * h + 0.001f) : 0.0f;
    float cw = fmaxf(r1, r2) - fminf(l1b, l2b);
    float ch = fmaxf(u1, u2) - fminf(d1, d2);
    float cw2 = cw * cw, ch2 = ch * ch;
    float dw = w1 - w2, dh = h1 - h2;
    float rho_w = dw * dw / (cw2 + 0.001f);
    float rho_h = dh * dh / (ch2 + 0.001f);
    float dx = x1 - x2, dy = y1 - y2;
    float rho_d = (dx * dx + dy * dy) / (cw2 + ch2 + 0.001f);
    float ce = 1.0f - iou + rho_d + rho_w + rho_h;

    out[oid] = 0.25f * cost_focal + 0.75f * cost_dice + cost_class
             + 0.8f * l1 + 0.2f * ce;
}

extern "C" void kernel_launch(void* const* d_in, const int* in_sizes, int n_in,
                              void* d_out, int out_size) {
    const float* pred_prob = (const float*)d_in[0];
    const float* pred_mask = (const float*)d_in[1];
    const float* pred_mom  = (const float*)d_in[2];
    const int*   tcls      = (const int*)d_in[3];
    const float* tmask     = (const float*)d_in[4];
    const float* tmom      = (const float*)d_in[5];
    float* out = (float*)d_out;

    static int configured = 0;
    if (!configured) {
        cudaFuncSetAttribute(k_dots, cudaFuncAttributeMaxDynamicSharedMemorySize,
                             DSMEM_BYTES);
        configured = 1;
    }

    k_pre<<<1700, 288>>>(pred_mask, tmask);
    dim3 grid(KSPLIT, B_);
    k_dots<<<grid, 512, DSMEM_BYTES>>>(tmask);
    int total_threads = 2 * B_ * N_ * M_;
    k_assemble<<<(total_threads + 255) / 256, 256>>>(pred_prob, pred_mom, tcls, tmom, out);
}

// round 17
// speedup vs baseline: 1.3183x; 1.3018x over previous
#include <cuda_runtime.h>
#include <math.h>

#define B_ 2
#define C_ 10
#define N_ 100
#define M_ 50
#define HW 9216      // 96*96
#define HPWP 576     // 24*24
#define KSPLIT 144
#define KC 64        // k per dots block
#define NQ 8
#define TSTR 68      // smem row stride (floats): conflict-free frags, 16B rows
#define SM_T 0
#define SM_P (56 * TSTR)              // 3808
#define SM_G (SM_P + 112 * TSTR)      // 11424
#define SM_TOT (SM_G + 112 * TSTR)    // 19040 floats = 76160 B
#define DSMEM_BYTES (SM_TOT * 4)
#define TWO_PI_F 6.2831854820251465f
#define PI_F 3.1415927410125732f

typedef unsigned int uint32;

// ---------------- scratch ----------------
__device__ __align__(16) float g_P[B_ * N_ * HW];
__device__ __align__(16) float g_G[B_ * N_ * HW];
__device__ __align__(16) float g_Sp[B_ * N_];
__device__ __align__(16) float g_F0c[B_ * N_ * NQ];
__device__ __align__(16) float g_St[B_ * M_];
// layout: [b][ks][n][m]
__device__ __align__(16) float g_part1[B_ * KSPLIT * N_ * M_];
__device__ __align__(16) float g_part2[B_ * KSPLIT * N_ * M_];

__constant__ float c_w[4] = {0.625f, 0.875f, 0.125f, 0.375f};

__device__ __forceinline__ float to_tf32(float x) {
    uint32 u;
    asm("cvt.rna.tf32.f32 %0, %1;" : "=r"(u) : "f"(x));
    return __uint_as_float(u);
}

#define MMA_TF32(c0, c1, c2, c3, a0, a1, a2, a3, b0, b1) \
    asm volatile("mma.sync.aligned.m16n8k8.row.col.f32.tf32.tf32.f32 " \
                 "{%0,%1,%2,%3}, {%4,%5,%6,%7}, {%8,%9}, {%0,%1,%2,%3};" \
                 : "+f"(c0), "+f"(c1), "+f"(c2), "+f"(c3) \
                 : "r"(a0), "r"(a1), "r"(a2), "r"(a3), "r"(b0), "r"(b1))

// paired reduce over 288 threads (9 warps); valid in thread 0
__device__ __forceinline__ float2 blockReduceSum2_288(float a, float b, float2* sh) {
    int lane = threadIdx.x & 31;
    int wid = threadIdx.x >> 5;
    #pragma unroll
    for (int o = 16; o > 0; o >>= 1) {
        a += __shfl_down_sync(0xffffffffu, a, o);
        b += __shfl_down_sync(0xffffffffu, b, o);
    }
    if (lane == 0) sh[wid] = make_float2(a, b);
    __syncthreads();
    float2 v = (threadIdx.x < 9) ? sh[threadIdx.x] : make_float2(0.f, 0.f);
    if (wid == 0) {
        #pragma unroll
        for (int o = 8; o > 0; o >>= 1) {
            v.x += __shfl_down_sync(0xffffffffu, v.x, o);
            v.y += __shfl_down_sync(0xffffffffu, v.y, o);
        }
    }
    return v;
}

// ------ kernel 1: St blocks 0..99 first, conv blocks 100..1699 ------
__global__ void __launch_bounds__(288) k_pre(const float* __restrict__ pred_mask,
                                             const float* __restrict__ tmask) {
    __shared__ float sm[HPWP];
    __shared__ float2 red2[9];
    int tid = threadIdx.x;
    int bc = blockIdx.x;

    if (bc < 100) {
        int bm = bc;
        const float4* src = (const float4*)(tmask + (size_t)bm * HW);
        float s = 0.0f;
        #pragma unroll
        for (int i = 0; i < 8; i++) {
            int idx = tid + i * 288;
            if (idx < HW / 4) {
                float4 v = src[idx];
                s += (fabsf(v.x) + fabsf(v.y)) + (fabsf(v.z) + fabsf(v.w));
            }
        }
        float2 ts = blockReduceSum2_288(s, 0.0f, red2);
        if (tid == 0) g_St[bm] = ts.x;
    } else {
        int cc = bc - 100;
        int bn = cc >> 3;
        int q  = cc & 7;

        float2 v2 = ((const float2*)(pred_mask + (size_t)bn * HPWP))[tid];
        *(float2*)(sm + (tid << 1)) = v2;
        float ssum = (q == 0) ? (v2.x + v2.y) : 0.0f;
        __syncthreads();

        float* Pout = g_P + (size_t)bn * HW + q * (12 * 96);
        float* Gout = g_G + (size_t)bn * HW + q * (12 * 96);

        int r = tid / 24;
        int j = tid - r * 24;
        int yg = q * 12 + r;
        int iy = (yg - 2) >> 2;
        float wy = c_w[yg & 3];
        int iy0 = max(iy, 0) * 24, iy1 = min(iy + 1, 23) * 24;
        int cm = max(j - 1, 0), cp = min(j + 1, 23);

        float a0 = sm[iy0 + cm], a1 = sm[iy0 + j], a2 = sm[iy0 + cp];
        float b0 = sm[iy1 + cm], b1 = sm[iy1 + j], b2 = sm[iy1 + cp];

        float t0 = a0 + 0.625f * (a1 - a0);
        float t1 = a0 + 0.875f * (a1 - a0);
        float t2 = a1 + 0.125f * (a2 - a1);
        float t3 = a1 + 0.375f * (a2 - a1);
        float u0 = b0 + 0.625f * (b1 - b0);
        float u1 = b0 + 0.875f * (b1 - b0);
        float u2 = b1 + 0.125f * (b2 - b1);
        float u3 = b1 + 0.375f * (b2 - b1);

        float pv[4];
        pv[0] = t0 + wy * (u0 - t0);
        pv[1] = t1 + wy * (u1 - t1);
        pv[2] = t2 + wy * (u2 - t2);
        pv[3] = t3 + wy * (u3 - t3);

        float gv[4];
        float sf0 = 0.0f;
        #pragma unroll
        for (int k = 0; k < 4; k++) {
            float pc = fminf(fmaxf(pv[k], 0.001f), 0.999f);
            float omc = 1.0f - pc;
            float f1 = 0.25f * (-__logf(pc)) * omc * omc;
            float f0 = 0.75f * (-__logf(omc)) * pc * pc;
            gv[k] = to_tf32(f1 - f0);
            sf0 += f0;
            pv[k] = to_tf32(pv[k]);
        }
        int o = r * 96 + j * 4;
        *(float4*)(Pout + o) = make_float4(pv[0], pv[1], pv[2], pv[3]);
        *(float4*)(Gout + o) = make_float4(gv[0], gv[1], gv[2], gv[3]);

        float2 ts = blockReduceSum2_288(sf0, ssum, red2);
        if (tid == 0) {
            g_F0c[bn * NQ + q] = ts.x;
            if (q == 0) g_Sp[bn] = 16.0f * ts.y;
        }
    }
}

// ------ kernel 2: dots via tf32 mma.sync ------
// grid (KSPLIT, B), 256 threads. smem: T 50x64, P 100x64, G 100x64 (stride 68)
__global__ void __launch_bounds__(256) k_dots(const float* __restrict__ tmask) {
    extern __shared__ __align__(16) float dsm[];
    int ks = blockIdx.x;
    int b  = blockIdx.y;
    int tid = threadIdx.x;
    int kbeg = ks * KC;

    const float* Tbase = tmask + (size_t)b * M_ * HW + kbeg;
    const float* Pbase = g_P + (size_t)b * N_ * HW + kbeg;
    const float* Gbase = g_G + (size_t)b * N_ * HW + kbeg;

    // ---- load tiles ----
    for (int e = tid; e < 800; e += 256) {
        int row = e >> 4, c4 = (e & 15) << 2;
        float4 v = *(const float4*)(Tbase + (size_t)row * HW + c4);
        *(float4*)(dsm + SM_T + row * TSTR + c4) = v;
    }
    for (int e = tid; e < 1600; e += 256) {
        int row = e >> 4, c4 = (e & 15) << 2;
        float4 v = *(const float4*)(Pbase + (size_t)row * HW + c4);
        *(float4*)(dsm + SM_P + row * TSTR + c4) = v;
        float4 w = *(const float4*)(Gbase + (size_t)row * HW + c4);
        *(float4*)(dsm + SM_G + row * TSTR + c4) = w;
    }
    __syncthreads();

    int w = tid >> 5;
    int lane = tid & 31;
    int g = lane >> 2;
    int tig = lane & 3;

    if (w < 7) {
        float cP[7][4], cG[7][4];
        #pragma unroll
        for (int nt = 0; nt < 7; nt++)
            #pragma unroll
            for (int i = 0; i < 4; i++) { cP[nt][i] = 0.f; cG[nt][i] = 0.f; }

        const float* smT = dsm + SM_T;
        const float* smP = dsm + SM_P + (16 * w + g) * TSTR;
        const float* smG = dsm + SM_G + (16 * w + g) * TSTR;
        const float* smTg = smT + g * TSTR;

        #pragma unroll
        for (int k8 = 0; k8 < 8; k8++) {
            int k0 = k8 * 8 + tig;
            uint32 aP0 = __float_as_uint(smP[k0]);
            uint32 aP1 = __float_as_uint(smP[8 * TSTR + k0]);
            uint32 aP2 = __float_as_uint(smP[k0 + 4]);
            uint32 aP3 = __float_as_uint(smP[8 * TSTR + k0 + 4]);
            uint32 aG0 = __float_as_uint(smG[k0]);
            uint32 aG1 = __float_as_uint(smG[8 * TSTR + k0]);
            uint32 aG2 = __float_as_uint(smG[k0 + 4]);
            uint32 aG3 = __float_as_uint(smG[8 * TSTR + k0 + 4]);
            #pragma unroll
            for (int nt = 0; nt < 7; nt++) {
                uint32 b0 = __float_as_uint(smTg[nt * 8 * TSTR + k0]);
                uint32 b1 = __float_as_uint(smTg[nt * 8 * TSTR + k0 + 4]);
                MMA_TF32(cP[nt][0], cP[nt][1], cP[nt][2], cP[nt][3],
                         aP0, aP1, aP2, aP3, b0, b1);
                MMA_TF32(cG[nt][0], cG[nt][1], cG[nt][2], cG[nt][3],
                         aG0, aG1, aG2, aG3, b0, b1);
            }
        }

        // ---- store: [b][ks][n][m], float2 (m, m+1) ----
        float* p1 = g_part1 + ((size_t)(b * KSPLIT + ks)) * (N_ * M_);
        float* p2 = g_part2 + ((size_t)(b * KSPLIT + ks)) * (N_ * M_);
        int n1 = 16 * w + g;
        int n2 = n1 + 8;
        #pragma unroll
        for (int nt = 0; nt < 7; nt++) {
            int m = nt * 8 + 2 * tig;
            if (m < 50) {
                if (n1 < 100) {
                    *(float2*)(p1 + n1 * M_ + m) = make_float2(cP[nt][0], cP[nt][1]);
                    *(float2*)(p2 + n1 * M_ + m) = make_float2(cG[nt][0], cG[nt][1]);
                }
                if (n2 < 100) {
                    *(float2*)(p1 + n2 * M_ + m) = make_float2(cP[nt][2], cP[nt][3]);
                    *(float2*)(p2 + n2 * M_ + m) = make_float2(cG[nt][2], cG[nt][3]);
                }
            }
        }
    }
}

// ------ kernel 3: assemble (2 threads per output) ------
__global__ void k_assemble(const float* __restrict__ pred_prob,
                           const float* __restrict__ pred_mom,
                           const int*   __restrict__ tcls,
                           const float* __restrict__ tmom,
                           float* __restrict__ out) {
    int gid = blockIdx.x * blockDim.x + threadIdx.x;
    int oid = gid >> 1;
    int part = gid & 1;
    bool valid = oid < B_ * N_ * M_;
    int o = valid ? oid : 0;
    int m = o % M_;
    int n = (o / M_) % N_;
    int b = o / (N_ * M_);

    // partials: [b][ks][n][m], this half-thread sums 72 ks values
    size_t base = ((size_t)(b * KSPLIT + part * (KSPLIT / 2)) * N_ + n) * M_ + m;
    float dot1 = 0.f, dot2 = 0.f;
    #pragma unroll 8
    for (int i = 0; i < KSPLIT / 2; i++) {
        dot1 += g_part1[base + (size_t)i * (N_ * M_)];
        dot2 += g_part2[base + (size_t)i * (N_ * M_)];
    }
    float f0s = 0.f;
    {
        const float4* pf = (const float4*)(g_F0c + (size_t)(b * N_ + n) * NQ + part * 4);
        float4 x = pf[0];
        f0s = (x.x + x.y) + (x.z + x.w);
    }
    dot1 += __shfl_down_sync(0xffffffffu, dot1, 1);
    dot2 += __shfl_down_sync(0xffffffffu, dot2, 1);
    f0s  += __shfl_down_sync(0xffffffffu, f0s, 1);

    if (!valid || part) return;

    int cls = tcls[b * M_ + m];
    if (cls <= 0) { out[oid] = 100000.0f; return; }

    float Sp = g_Sp[b * N_ + n];
    float St = g_St[b * M_ + m];
    float pos = Sp + St;
    float cost_dice = 1.0f - 2.0f * dot1 / (pos + 0.001f);
    float cost_focal = (f0s + dot2) * (1.0f / (float)HW);
    float cost_class = -pred_prob[((size_t)b * C_ + cls) * N_ + n];

    const float* pmv = pred_mom + (size_t)(b * N_ + n) * 4;
    float p0 = __expf(fminf(pmv[0], 10.0f));
    float p1f = TWO_PI_F / (1.0f + __expf(-pmv[1]));
    float p2f = TWO_PI_F / (1.0f + __expf(-pmv[2]));
    float p3 = __expf(fminf(pmv[3], 10.0f));
    const float* tmv = tmom + (size_t)(b * M_ + m) * 4;
    float t0 = tmv[0], t1 = tmv[1], t2 = tmv[2], t3 = tmv[3];

    float pe = (t2 - p2f > PI_F) ? TWO_PI_F : 0.0f;
    float te = (p2f - t2 > PI_F) ? TWO_PI_F : 0.0f;
    float l1 = (fabsf(p0 / (t0 + 0.001f) - 1.0f)
              + fabsf(p1f / (t1 + 0.001f) - 1.0f)
              + fabsf((p2f + pe) / (t2 + te + 0.001f) - 1.0f)
              + fabsf(p3 / (t3 + 0.001f) - 1.0f)) * 0.25f;

    float w1 = p0, x1 = p1f, y1 = p2f, h1 = p3;
    float w2 = t0, x2 = t1, y2 = t2, h2 = t3;
    float y1e = (y2 - y1 > PI_F) ? TWO_PI_F : 0.0f;
    float y2e = (y1 - y2 > PI_F) ? TWO_PI_F : 0.0f;
    y1 += y1e;
    y2 += y2e;
    float r1 = x1 + w1 * 0.5f, l1b = x1 - w1 * 0.5f;
    float r2 = x2 + w2 * 0.5f, l2b = x2 - w2 * 0.5f;
    float u1 = y1 + h1 * 0.5f, d1 = y1 - h1 * 0.5f;
    float u2 = y2 + h2 * 0.5f, d2 = y2 - h2 * 0.5f;
    float w = fminf(r1, r2) - fmaxf(l1b, l2b);
    float h = fminf(u1, u2) - fmaxf(d1, d2);
    float iou = (w > 0.0f && h > 0.0f)
                ? (w * h) / (w1 * h1 + w2 * h2 - w * h + 0.001f) : 0.0f;
    float cw = fmaxf(r1, r2) - fminf(l1b, l2b);
    float ch = fmaxf(u1, u2) - fminf(d1, d2);
    float cw2 = cw * cw, ch2 = ch * ch;
    float dw = w1 - w2, dh = h1 - h2;
    float rho_w = dw * dw / (cw2 + 0.001f);
    float rho_h = dh * dh / (ch2 + 0.001f);
    float dx = x1 - x2, dy = y1 - y2;
    float rho_d = (dx * dx + dy * dy) / (cw2 + ch2 + 0.001f);
    float ce = 1.0f - iou + rho_d + rho_w + rho_h;

    out[oid] = 0.25f * cost_focal + 0.75f * cost_dice + cost_class
             + 0.8f * l1 + 0.2f * ce;
}

extern "C" void kernel_launch(void* const* d_in, const int* in_sizes, int n_in,
                              void* d_out, int out_size) {
    const float* pred_prob = (const float*)d_in[0];
    const float* pred_mask = (const float*)d_in[1];
    const float* pred_mom  = (const float*)d_in[2];
    const int*   tcls      = (const int*)d_in[3];
    const float* tmask     = (const float*)d_in[4];
    const float* tmom      = (const float*)d_in[5];
    float* out = (float*)d_out;

    static int configured = 0;
    if (!configured) {
        cudaFuncSetAttribute(k_dots, cudaFuncAttributeMaxDynamicSharedMemorySize,
                             DSMEM_BYTES);
        configured = 1;
    }

    k_pre<<<1700, 288>>>(pred_mask, tmask);
    dim3 grid(KSPLIT, B_);
    k_dots<<<grid, 256, DSMEM_BYTES>>>(tmask);
    int total_threads = 2 * B_ * N_ * M_;
    k_assemble<<<(total_threads + 255) / 256, 256>>>(pred_prob, pred_mom, tcls, tmom, out);
}